// round 7
// baseline (speedup 1.0000x reference)
#include <cuda_runtime.h>
#include <cuda_fp16.h>

#define BB 16
#define CC 192
#define HH 64
#define WW 64
#define LL (HH*WW)      // 4096
#define RR 12           // dt_rank
#define NK 14           // dt_rank + 2*d_state

#define NGRP 4
#define GB   (BB / NGRP)   // 4 batches per pipeline group

// Scratch (no cudaMalloc allowed)
__device__ float  g_xs[(size_t)BB*CC*LL];       // 50.3 MB  conv+SiLU output
__device__ __half g_delta_h[(size_t)BB*CC*LL];  // 25.2 MB  softplus(dt-proj), fp16
__device__ float  g_bc[(size_t)BB*2*LL];        // 0.5 MB   Bs, Cs rows

// ---------------------------------------------------------------------------
// K1: depthwise 5x5 conv (SAME) + bias + SiLU.  (R4/R6 form.)
// ---------------------------------------------------------------------------
__global__ __launch_bounds__(256) void conv_silu_kernel(
    const float* __restrict__ x,
    const float* __restrict__ cw,
    const float* __restrict__ cb,
    int bc0)
{
    int bc = blockIdx.x + bc0;      // b*CC + c
    int c  = bc % CC;
    __shared__ float s[68 * 68];
    const float* img = x + (size_t)bc * LL;
    int tid = threadIdx.x;

    for (int idx = tid; idx < 68 * 68; idx += 256) {
        int yy = idx / 68, xx = idx % 68;
        int iy = yy - 2, ix = xx - 2;
        float v = 0.f;
        if (iy >= 0 && iy < HH && ix >= 0 && ix < WW) v = img[iy * WW + ix];
        s[idx] = v;
    }

    float w[25];
#pragma unroll
    for (int i = 0; i < 25; i++) w[i] = __ldg(&cw[c * 25 + i]);
    float bias = __ldg(&cb[c]);
    __syncthreads();

    int xcol = tid & 63;
    int y0   = (tid >> 6) * 16;
    float* dst = g_xs + (size_t)bc * LL;

    float win[5][5];
#pragma unroll
    for (int dy = 0; dy < 4; dy++)
#pragma unroll
        for (int dx = 0; dx < 5; dx++)
            win[dy][dx] = s[(y0 + dy) * 68 + xcol + dx];

#pragma unroll
    for (int i = 0; i < 16; i++) {
        int y = y0 + i;
#pragma unroll
        for (int dx = 0; dx < 5; dx++)
            win[4][dx] = s[(y + 4) * 68 + xcol + dx];

        float acc0 = bias, acc1 = 0.f;
#pragma unroll
        for (int dy = 0; dy < 5; dy++) {
#pragma unroll
            for (int dx = 0; dx < 5; dx++) {
                if (((dy * 5 + dx) & 1) == 0) acc0 = fmaf(win[dy][dx], w[dy*5+dx], acc0);
                else                          acc1 = fmaf(win[dy][dx], w[dy*5+dx], acc1);
            }
        }
        float acc = acc0 + acc1;

        float e = exp2f(-acc * 1.44269504f);
        dst[y * WW + xcol] = __fdividef(acc, 1.f + e);

#pragma unroll
        for (int dy = 0; dy < 4; dy++)
#pragma unroll
            for (int dx = 0; dx < 5; dx++)
                win[dy][dx] = win[dy + 1][dx];
    }
}

// ---------------------------------------------------------------------------
// K2: fused x_proj + dt-projection + softplus (R6 form), fp16 delta output.
// ---------------------------------------------------------------------------
__global__ __launch_bounds__(256) void xproj_delta_kernel(
    const float* __restrict__ xw,     // (14, C)
    const float* __restrict__ dtw,    // (C, 12)
    const float* __restrict__ dtb,    // (C,)
    int b0)
{
    __shared__ float sw[CC * 16];
    __shared__ float sdt[CC * RR];
    __shared__ float sdb[CC];
    int t = threadIdx.x;
    for (int i = t; i < CC * 16; i += 256) sw[i] = 0.f;
    __syncthreads();
    for (int i = t; i < NK * CC; i += 256) {
        int k = i / CC, c = i % CC;
        sw[c * 16 + k] = xw[i];
    }
    for (int i = t; i < CC * RR; i += 256) sdt[i] = dtw[i];
    for (int i = t; i < CC; i += 256) sdb[i] = dtb[i];
    __syncthreads();

    int half = t & 1;
    int b = blockIdx.y + b0;
    int l0 = blockIdx.x * 256 + (t >> 1) * 2;
    const float* xs = g_xs + (size_t)b * CC * LL + l0;
    int c0 = half * 96;

    float accx[NK], accy[NK];
#pragma unroll
    for (int k = 0; k < NK; k++) { accx[k] = 0.f; accy[k] = 0.f; }

#pragma unroll 8
    for (int ci = 0; ci < 96; ci++) {
        int c = c0 + ci;
        float2 v = *(const float2*)(xs + (size_t)c * LL);
        const float4* wp4 = (const float4*)&sw[c * 16];
        float4 w0 = wp4[0], w1 = wp4[1], w2 = wp4[2], w3 = wp4[3];
        accx[0]  = fmaf(w0.x, v.x, accx[0]);  accy[0]  = fmaf(w0.x, v.y, accy[0]);
        accx[1]  = fmaf(w0.y, v.x, accx[1]);  accy[1]  = fmaf(w0.y, v.y, accy[1]);
        accx[2]  = fmaf(w0.z, v.x, accx[2]);  accy[2]  = fmaf(w0.z, v.y, accy[2]);
        accx[3]  = fmaf(w0.w, v.x, accx[3]);  accy[3]  = fmaf(w0.w, v.y, accy[3]);
        accx[4]  = fmaf(w1.x, v.x, accx[4]);  accy[4]  = fmaf(w1.x, v.y, accy[4]);
        accx[5]  = fmaf(w1.y, v.x, accx[5]);  accy[5]  = fmaf(w1.y, v.y, accy[5]);
        accx[6]  = fmaf(w1.z, v.x, accx[6]);  accy[6]  = fmaf(w1.z, v.y, accy[6]);
        accx[7]  = fmaf(w1.w, v.x, accx[7]);  accy[7]  = fmaf(w1.w, v.y, accy[7]);
        accx[8]  = fmaf(w2.x, v.x, accx[8]);  accy[8]  = fmaf(w2.x, v.y, accy[8]);
        accx[9]  = fmaf(w2.y, v.x, accx[9]);  accy[9]  = fmaf(w2.y, v.y, accy[9]);
        accx[10] = fmaf(w2.z, v.x, accx[10]); accy[10] = fmaf(w2.z, v.y, accy[10]);
        accx[11] = fmaf(w2.w, v.x, accx[11]); accy[11] = fmaf(w2.w, v.y, accy[11]);
        accx[12] = fmaf(w3.x, v.x, accx[12]); accy[12] = fmaf(w3.x, v.y, accy[12]);
        accx[13] = fmaf(w3.y, v.x, accx[13]); accy[13] = fmaf(w3.y, v.y, accy[13]);
    }

#pragma unroll
    for (int k = 0; k < NK; k++) {
        accx[k] += __shfl_xor_sync(0xffffffffu, accx[k], 1);
        accy[k] += __shfl_xor_sync(0xffffffffu, accy[k], 1);
    }

    if (half == 0) {
        float* bcp = g_bc + (size_t)b * 2 * LL + l0;
        *(float2*)bcp        = make_float2(accx[12], accy[12]);
        *(float2*)(bcp + LL) = make_float2(accx[13], accy[13]);
    }

    __half* dl = g_delta_h + (size_t)b * CC * LL + l0;
#pragma unroll 4
    for (int ci = 0; ci < 96; ci++) {
        int c = c0 + ci;
        const float4* dwp = (const float4*)&sdt[c * RR];
        float4 d0 = dwp[0], d1 = dwp[1], d2 = dwp[2];
        float dxv = sdb[c], dyv = sdb[c];
        dxv = fmaf(d0.x, accx[0], dxv); dyv = fmaf(d0.x, accy[0], dyv);
        dxv = fmaf(d0.y, accx[1], dxv); dyv = fmaf(d0.y, accy[1], dyv);
        dxv = fmaf(d0.z, accx[2], dxv); dyv = fmaf(d0.z, accy[2], dyv);
        dxv = fmaf(d0.w, accx[3], dxv); dyv = fmaf(d0.w, accy[3], dyv);
        dxv = fmaf(d1.x, accx[4], dxv); dyv = fmaf(d1.x, accy[4], dyv);
        dxv = fmaf(d1.y, accx[5], dxv); dyv = fmaf(d1.y, accy[5], dyv);
        dxv = fmaf(d1.z, accx[6], dxv); dyv = fmaf(d1.z, accy[6], dyv);
        dxv = fmaf(d1.w, accx[7], dxv); dyv = fmaf(d1.w, accy[7], dyv);
        dxv = fmaf(d2.x, accx[8], dxv); dyv = fmaf(d2.x, accy[8], dyv);
        dxv = fmaf(d2.y, accx[9], dxv); dyv = fmaf(d2.y, accy[9], dyv);
        dxv = fmaf(d2.z, accx[10], dxv); dyv = fmaf(d2.z, accy[10], dyv);
        dxv = fmaf(d2.w, accx[11], dxv); dyv = fmaf(d2.w, accy[11], dyv);

        float tx = __log2f(1.f + exp2f(dxv * 1.44269504f)) * 0.69314718f;
        float ty = __log2f(1.f + exp2f(dyv * 1.44269504f)) * 0.69314718f;
        float spx = (dxv > 20.f) ? dxv : tx;
        float spy = (dyv > 20.f) ? dyv : ty;
        *(__half2*)(dl + (size_t)c * LL) = __floats2half2_rn(spx, spy);
    }
}

// ---------------------------------------------------------------------------
// K3: selective scan (d_state=1) + output (R6 warp-striped form, fp16 delta).
// ---------------------------------------------------------------------------
#define TPB3 256
#define NCH  4

__global__ __launch_bounds__(TPB3) void scan_kernel(
    const float* __restrict__ A_logs,
    const float* __restrict__ Ds,
    float* __restrict__ out,
    int bc0)
{
    int bc = blockIdx.x + bc0;
    int b = bc / CC, c = bc % CC;
    int t = threadIdx.x;
    int lane = t & 31, wid = t >> 5;
    int wbase = wid * 512;

    const float*  xs_row = g_xs      + (size_t)bc * LL;
    const __half* dl_row = g_delta_h + (size_t)bc * LL;
    const float*  Bs_row = g_bc + (size_t)b * 2 * LL;
    const float*  Cs_row = Bs_row + LL;

    float Dv  = __ldg(&Ds[c]);
    float Al2 = -1.44269504f * __expf(__ldg(&A_logs[c]));

    float dv[NCH][4], xv[NCH][4], bv[NCH][4];
    float Ain[NCH], Bin[NCH];
    float carryA = 1.f, carryB = 0.f;

#pragma unroll
    for (int j = 0; j < NCH; j++) {
        int l = wbase + j * 128 + lane * 4;
        uint2 raw = *(const uint2*)(dl_row + l);
        float2 f01 = __half22float2(*(__half2*)&raw.x);
        float2 f23 = __half22float2(*(__half2*)&raw.y);
        dv[j][0]=f01.x; dv[j][1]=f01.y; dv[j][2]=f23.x; dv[j][3]=f23.y;
        float4 x4 = *(const float4*)(xs_row + l);
        float4 b4 = *(const float4*)(Bs_row + l);
        xv[j][0]=x4.x; xv[j][1]=x4.y; xv[j][2]=x4.z; xv[j][3]=x4.w;
        bv[j][0]=b4.x; bv[j][1]=b4.y; bv[j][2]=b4.z; bv[j][3]=b4.w;

        float Ac = 1.f, Bc = 0.f;
#pragma unroll
        for (int k = 0; k < 4; k++) {
            float a  = exp2f(Al2 * dv[j][k]);
            float bt = dv[j][k] * bv[j][k] * xv[j][k];
            Ac = a * Ac;
            Bc = fmaf(a, Bc, bt);
        }

        float Asc = Ac, Bsc = Bc;
#pragma unroll
        for (int off = 1; off < 32; off <<= 1) {
            float aU = __shfl_up_sync(0xffffffffu, Asc, off);
            float bU = __shfl_up_sync(0xffffffffu, Bsc, off);
            if (lane >= off) { Bsc = fmaf(Asc, bU, Bsc); Asc *= aU; }
        }
        float aEx = __shfl_up_sync(0xffffffffu, Asc, 1);
        float bEx = __shfl_up_sync(0xffffffffu, Bsc, 1);
        if (lane == 0) { aEx = 1.f; bEx = 0.f; }
        Ain[j] = aEx * carryA;
        Bin[j] = fmaf(aEx, carryB, bEx);
        float aT = __shfl_sync(0xffffffffu, Asc, 31);
        float bT = __shfl_sync(0xffffffffu, Bsc, 31);
        carryB = fmaf(aT, carryB, bT);
        carryA = aT * carryA;
    }

    __shared__ float swA[TPB3/32], swB[TPB3/32];
    if (lane == 0) { swA[wid] = carryA; swB[wid] = carryB; }
    __syncthreads();
    float Hws = 0.f;
    for (int wp = 0; wp < wid; wp++) Hws = fmaf(swA[wp], Hws, swB[wp]);

    float* out_row = out + (size_t)bc * LL;
#pragma unroll
    for (int j = 0; j < NCH; j++) {
        int l = wbase + j * 128 + lane * 4;
        float4 c4 = *(const float4*)(Cs_row + l);
        float csv[4] = {c4.x, c4.y, c4.z, c4.w};
        float h = fmaf(Ain[j], Hws, Bin[j]);
        float yo[4];
#pragma unroll
        for (int k = 0; k < 4; k++) {
            float a = exp2f(Al2 * dv[j][k]);
            h = fmaf(a, h, dv[j][k] * bv[j][k] * xv[j][k]);
            yo[k] = fmaf(h, csv[k], xv[j][k] * Dv);
        }
        *(float4*)(out_row + l) = make_float4(yo[0], yo[1], yo[2], yo[3]);
    }
}

// ---------------------------------------------------------------------------
// Pipelined launch: 4 batch-groups on 3 non-blocking streams, fork-join from
// the (captured) legacy stream via events. Host-side resources created once;
// identical work every call (graph-capturable, no device allocation).
// ---------------------------------------------------------------------------
extern "C" void kernel_launch(void* const* d_in, const int* in_sizes, int n_in,
                              void* d_out, int out_size)
{
    const float* x        = (const float*)d_in[0];
    const float* conv_w   = (const float*)d_in[1];
    const float* conv_b   = (const float*)d_in[2];
    const float* x_proj_w = (const float*)d_in[3];
    const float* dt_w     = (const float*)d_in[4];
    const float* dt_b     = (const float*)d_in[5];
    const float* A_logs   = (const float*)d_in[6];
    const float* Ds       = (const float*)d_in[7];
    float* out = (float*)d_out;

    static cudaStream_t st[3];
    static cudaEvent_t  evRoot, evFin;
    static cudaEvent_t  e1[NGRP], e2[NGRP];
    static bool ready = false;
    static bool use_streams = false;
    if (!ready) {
        bool ok = true;
        for (int i = 0; i < 3; i++)
            ok &= (cudaStreamCreateWithFlags(&st[i], cudaStreamNonBlocking) == cudaSuccess);
        ok &= (cudaEventCreateWithFlags(&evRoot, cudaEventDisableTiming) == cudaSuccess);
        ok &= (cudaEventCreateWithFlags(&evFin,  cudaEventDisableTiming) == cudaSuccess);
        for (int g = 0; g < NGRP; g++) {
            ok &= (cudaEventCreateWithFlags(&e1[g], cudaEventDisableTiming) == cudaSuccess);
            ok &= (cudaEventCreateWithFlags(&e2[g], cudaEventDisableTiming) == cudaSuccess);
        }
        use_streams = ok;
        ready = true;
    }

    if (use_streams) {
        cudaEventRecord(evRoot, 0);                 // fork from captured stream
        cudaStreamWaitEvent(st[0], evRoot, 0);
        cudaStreamWaitEvent(st[1], evRoot, 0);
        cudaStreamWaitEvent(st[2], evRoot, 0);

        for (int g = 0; g < NGRP; g++) {
            int b0  = g * GB;
            int bc0 = b0 * CC;
            conv_silu_kernel<<<GB * CC, 256, 0, st[0]>>>(x, conv_w, conv_b, bc0);
            cudaEventRecord(e1[g], st[0]);
            cudaStreamWaitEvent(st[1], e1[g], 0);
            xproj_delta_kernel<<<dim3(LL / 256, GB), 256, 0, st[1]>>>(x_proj_w, dt_w, dt_b, b0);
            cudaEventRecord(e2[g], st[1]);
            cudaStreamWaitEvent(st[2], e2[g], 0);
            scan_kernel<<<GB * CC, TPB3, 0, st[2]>>>(A_logs, Ds, out, bc0);
        }

        cudaEventRecord(evFin, st[2]);              // join back into captured stream
        cudaStreamWaitEvent(0, evFin, 0);
    } else {
        conv_silu_kernel<<<BB * CC, 256>>>(x, conv_w, conv_b, 0);
        xproj_delta_kernel<<<dim3(LL / 256, BB), 256>>>(x_proj_w, dt_w, dt_b, 0);
        scan_kernel<<<BB * CC, TPB3>>>(A_logs, Ds, out, 0);
    }
}

// round 9
// speedup vs baseline: 2.1570x; 2.1570x over previous
#include <cuda_runtime.h>
#include <cuda_fp16.h>

#define BB 16
#define CC 192
#define HH 64
#define WW 64
#define LL (HH*WW)      // 4096
#define RR 12           // dt_rank
#define NK 14           // dt_rank + 2*d_state

// Scratch (no cudaMalloc allowed)
__device__ float  g_xs[(size_t)BB*CC*LL];       // 50.3 MB  conv+SiLU output
__device__ __half g_delta_h[(size_t)BB*CC*LL];  // 25.2 MB  softplus(dt-proj), fp16
__device__ float  g_bc[(size_t)BB*2*LL];        // 0.5 MB   Bs, Cs rows

// ---------------------------------------------------------------------------
// K1: depthwise 5x5 conv (SAME) + bias + SiLU.  (R6 form, unchanged.)
// ---------------------------------------------------------------------------
__global__ __launch_bounds__(256) void conv_silu_kernel(
    const float* __restrict__ x,
    const float* __restrict__ cw,
    const float* __restrict__ cb)
{
    int bc = blockIdx.x;            // b*CC + c
    int c  = bc % CC;
    __shared__ float s[68 * 68];
    const float* img = x + (size_t)bc * LL;
    int tid = threadIdx.x;

    for (int idx = tid; idx < 68 * 68; idx += 256) {
        int yy = idx / 68, xx = idx % 68;
        int iy = yy - 2, ix = xx - 2;
        float v = 0.f;
        if (iy >= 0 && iy < HH && ix >= 0 && ix < WW) v = img[iy * WW + ix];
        s[idx] = v;
    }

    float w[25];
#pragma unroll
    for (int i = 0; i < 25; i++) w[i] = __ldg(&cw[c * 25 + i]);
    float bias = __ldg(&cb[c]);
    __syncthreads();

    int xcol = tid & 63;
    int y0   = (tid >> 6) * 16;
    float* dst = g_xs + (size_t)bc * LL;

    float win[5][5];
#pragma unroll
    for (int dy = 0; dy < 4; dy++)
#pragma unroll
        for (int dx = 0; dx < 5; dx++)
            win[dy][dx] = s[(y0 + dy) * 68 + xcol + dx];

#pragma unroll
    for (int i = 0; i < 16; i++) {
        int y = y0 + i;
#pragma unroll
        for (int dx = 0; dx < 5; dx++)
            win[4][dx] = s[(y + 4) * 68 + xcol + dx];

        float acc0 = bias, acc1 = 0.f;
#pragma unroll
        for (int dy = 0; dy < 5; dy++) {
#pragma unroll
            for (int dx = 0; dx < 5; dx++) {
                if (((dy * 5 + dx) & 1) == 0) acc0 = fmaf(win[dy][dx], w[dy*5+dx], acc0);
                else                          acc1 = fmaf(win[dy][dx], w[dy*5+dx], acc1);
            }
        }
        float acc = acc0 + acc1;

        float e = exp2f(-acc * 1.44269504f);
        dst[y * WW + xcol] = __fdividef(acc, 1.f + e);

#pragma unroll
        for (int dy = 0; dy < 4; dy++)
#pragma unroll
            for (int dx = 0; dx < 5; dx++)
                win[dy][dx] = win[dy + 1][dx];
    }
}

// ---------------------------------------------------------------------------
// K2: fused x_proj + dt-projection + softplus, fp16 delta output.
// 2-way lane split with INTERLEAVED weight layout [ci][half][16]:
// the pair's two LDS addresses differ by 64B -> different banks, single-phase
// broadcast (the old layout put them 6144/4608B apart -> same bank, 2-phase).
// 1 l per thread, block covers 128 l's -> grid (32,16)=512 blocks (2x warps/SM).
// ---------------------------------------------------------------------------
__global__ __launch_bounds__(256) void xproj_delta_kernel(
    const float* __restrict__ xw,     // (14, C)
    const float* __restrict__ dtw,    // (C, 12)
    const float* __restrict__ dtb)    // (C,)
{
    __shared__ float sw [96 * 32];    // [ci][half][16]  x_proj_w^T, padded
    __shared__ float sdt[96 * 32];    // [ci][half][16]  dt_w rows (12 used)
    __shared__ float sdb[CC];
    int t = threadIdx.x;
    for (int i = t; i < 96 * 32; i += 256) { sw[i] = 0.f; sdt[i] = 0.f; }
    __syncthreads();
    for (int i = t; i < NK * CC; i += 256) {
        int k = i / CC, c = i % CC;
        int ci = c % 96, hf = c / 96;
        sw[ci * 32 + hf * 16 + k] = xw[i];
    }
    for (int i = t; i < CC * RR; i += 256) {
        int c = i / RR, r = i % RR;
        int ci = c % 96, hf = c / 96;
        sdt[ci * 32 + hf * 16 + r] = dtw[i];
    }
    for (int i = t; i < CC; i += 256) sdb[i] = dtb[i];
    __syncthreads();

    int half = t & 1;                 // lane pair shares one l
    int li   = t >> 1;                // 0..127
    int b = blockIdx.y;
    int l = blockIdx.x * 128 + li;
    const float* xs = g_xs + (size_t)b * CC * LL + l;
    int cbase = half * 96;

    float acc[NK];
#pragma unroll
    for (int k = 0; k < NK; k++) acc[k] = 0.f;

#pragma unroll 8
    for (int ci = 0; ci < 96; ci++) {
        int c = cbase + ci;
        float v = xs[(size_t)c * LL];
        const float4* wp4 = (const float4*)&sw[ci * 32 + half * 16];
        float4 w0 = wp4[0], w1 = wp4[1], w2 = wp4[2], w3 = wp4[3];
        acc[0]  = fmaf(w0.x, v, acc[0]);
        acc[1]  = fmaf(w0.y, v, acc[1]);
        acc[2]  = fmaf(w0.z, v, acc[2]);
        acc[3]  = fmaf(w0.w, v, acc[3]);
        acc[4]  = fmaf(w1.x, v, acc[4]);
        acc[5]  = fmaf(w1.y, v, acc[5]);
        acc[6]  = fmaf(w1.z, v, acc[6]);
        acc[7]  = fmaf(w1.w, v, acc[7]);
        acc[8]  = fmaf(w2.x, v, acc[8]);
        acc[9]  = fmaf(w2.y, v, acc[9]);
        acc[10] = fmaf(w2.z, v, acc[10]);
        acc[11] = fmaf(w2.w, v, acc[11]);
        acc[12] = fmaf(w3.x, v, acc[12]);
        acc[13] = fmaf(w3.y, v, acc[13]);
    }

    // combine the two c-halves (partner lane = lane^1)
#pragma unroll
    for (int k = 0; k < NK; k++)
        acc[k] += __shfl_xor_sync(0xffffffffu, acc[k], 1);

    if (half == 0) {
        float* bcp = g_bc + (size_t)b * 2 * LL + l;
        bcp[0]  = acc[12];
        bcp[LL] = acc[13];
    }

    __half* dl = g_delta_h + (size_t)b * CC * LL + l;
#pragma unroll 4
    for (int ci = 0; ci < 96; ci++) {
        int c = cbase + ci;
        const float4* dwp = (const float4*)&sdt[ci * 32 + half * 16];
        float4 d0 = dwp[0], d1 = dwp[1], d2 = dwp[2];
        float dxv = sdb[c];
        dxv = fmaf(d0.x, acc[0], dxv);
        dxv = fmaf(d0.y, acc[1], dxv);
        dxv = fmaf(d0.z, acc[2], dxv);
        dxv = fmaf(d0.w, acc[3], dxv);
        dxv = fmaf(d1.x, acc[4], dxv);
        dxv = fmaf(d1.y, acc[5], dxv);
        dxv = fmaf(d1.z, acc[6], dxv);
        dxv = fmaf(d1.w, acc[7], dxv);
        dxv = fmaf(d2.x, acc[8], dxv);
        dxv = fmaf(d2.y, acc[9], dxv);
        dxv = fmaf(d2.z, acc[10], dxv);
        dxv = fmaf(d2.w, acc[11], dxv);

        float tx  = __log2f(1.f + exp2f(dxv * 1.44269504f)) * 0.69314718f;
        float spx = (dxv > 20.f) ? dxv : tx;
        dl[(size_t)c * LL] = __float2half_rn(spx);
    }
}

// ---------------------------------------------------------------------------
// K3: selective scan (d_state=1) + output (R6 warp-striped form, unchanged).
// ---------------------------------------------------------------------------
#define TPB3 256
#define NCH  4

__global__ __launch_bounds__(TPB3) void scan_kernel(
    const float* __restrict__ A_logs,
    const float* __restrict__ Ds,
    float* __restrict__ out)
{
    int bc = blockIdx.x;
    int b = bc / CC, c = bc % CC;
    int t = threadIdx.x;
    int lane = t & 31, wid = t >> 5;
    int wbase = wid * 512;

    const float*  xs_row = g_xs      + (size_t)bc * LL;
    const __half* dl_row = g_delta_h + (size_t)bc * LL;
    const float*  Bs_row = g_bc + (size_t)b * 2 * LL;
    const float*  Cs_row = Bs_row + LL;

    float Dv  = __ldg(&Ds[c]);
    float Al2 = -1.44269504f * __expf(__ldg(&A_logs[c]));

    float dv[NCH][4], xv[NCH][4], bv[NCH][4];
    float Ain[NCH], Bin[NCH];
    float carryA = 1.f, carryB = 0.f;

#pragma unroll
    for (int j = 0; j < NCH; j++) {
        int l = wbase + j * 128 + lane * 4;
        uint2 raw = *(const uint2*)(dl_row + l);
        float2 f01 = __half22float2(*(__half2*)&raw.x);
        float2 f23 = __half22float2(*(__half2*)&raw.y);
        dv[j][0]=f01.x; dv[j][1]=f01.y; dv[j][2]=f23.x; dv[j][3]=f23.y;
        float4 x4 = *(const float4*)(xs_row + l);
        float4 b4 = *(const float4*)(Bs_row + l);
        xv[j][0]=x4.x; xv[j][1]=x4.y; xv[j][2]=x4.z; xv[j][3]=x4.w;
        bv[j][0]=b4.x; bv[j][1]=b4.y; bv[j][2]=b4.z; bv[j][3]=b4.w;

        float Ac = 1.f, Bc = 0.f;
#pragma unroll
        for (int k = 0; k < 4; k++) {
            float a  = exp2f(Al2 * dv[j][k]);
            float bt = dv[j][k] * bv[j][k] * xv[j][k];
            Ac = a * Ac;
            Bc = fmaf(a, Bc, bt);
        }

        float Asc = Ac, Bsc = Bc;
#pragma unroll
        for (int off = 1; off < 32; off <<= 1) {
            float aU = __shfl_up_sync(0xffffffffu, Asc, off);
            float bU = __shfl_up_sync(0xffffffffu, Bsc, off);
            if (lane >= off) { Bsc = fmaf(Asc, bU, Bsc); Asc *= aU; }
        }
        float aEx = __shfl_up_sync(0xffffffffu, Asc, 1);
        float bEx = __shfl_up_sync(0xffffffffu, Bsc, 1);
        if (lane == 0) { aEx = 1.f; bEx = 0.f; }
        Ain[j] = aEx * carryA;
        Bin[j] = fmaf(aEx, carryB, bEx);
        float aT = __shfl_sync(0xffffffffu, Asc, 31);
        float bT = __shfl_sync(0xffffffffu, Bsc, 31);
        carryB = fmaf(aT, carryB, bT);
        carryA = aT * carryA;
    }

    __shared__ float swA[TPB3/32], swB[TPB3/32];
    if (lane == 0) { swA[wid] = carryA; swB[wid] = carryB; }
    __syncthreads();
    float Hws = 0.f;
    for (int wp = 0; wp < wid; wp++) Hws = fmaf(swA[wp], Hws, swB[wp]);

    float* out_row = out + (size_t)bc * LL;
#pragma unroll
    for (int j = 0; j < NCH; j++) {
        int l = wbase + j * 128 + lane * 4;
        float4 c4 = *(const float4*)(Cs_row + l);
        float csv[4] = {c4.x, c4.y, c4.z, c4.w};
        float h = fmaf(Ain[j], Hws, Bin[j]);
        float yo[4];
#pragma unroll
        for (int k = 0; k < 4; k++) {
            float a = exp2f(Al2 * dv[j][k]);
            h = fmaf(a, h, dv[j][k] * bv[j][k] * xv[j][k]);
            yo[k] = fmaf(h, csv[k], xv[j][k] * Dv);
        }
        *(float4*)(out_row + l) = make_float4(yo[0], yo[1], yo[2], yo[3]);
    }
}

// ---------------------------------------------------------------------------
extern "C" void kernel_launch(void* const* d_in, const int* in_sizes, int n_in,
                              void* d_out, int out_size)
{
    const float* x        = (const float*)d_in[0];
    const float* conv_w   = (const float*)d_in[1];
    const float* conv_b   = (const float*)d_in[2];
    const float* x_proj_w = (const float*)d_in[3];
    const float* dt_w     = (const float*)d_in[4];
    const float* dt_b     = (const float*)d_in[5];
    const float* A_logs   = (const float*)d_in[6];
    const float* Ds       = (const float*)d_in[7];
    float* out = (float*)d_out;

    conv_silu_kernel<<<BB * CC, 256>>>(x, conv_w, conv_b);
    xproj_delta_kernel<<<dim3(LL / 128, BB), 256>>>(x_proj_w, dt_w, dt_b);
    scan_kernel<<<BB * CC, TPB3>>>(A_logs, Ds, out);
}